// round 15
// baseline (speedup 1.0000x reference)
#include <cuda_runtime.h>
#include <cuda_fp16.h>
#include <math.h>

#define BB   2
#define TT   1024
#define CC   2048
#define NH   16
#define HS   128
#define NLQ  512
#define NLKV 512
#define DHR  64
#define KCAT 576

// ---------------- fp32 scratch ----------------
__device__ float g_cq  [2048l * 512];
__device__ float g_ckr [2048l * 64];
__device__ float g_cqr [2048l * 1024];
__device__ float g_kcat[2048l * 576];
__device__ float g_veff[2048l * 512];
__device__ float g_attn[32l * 1024 * 1024];

// ---------------- fp16 scratch (all GEMM operands K-contiguous) ----------
__device__ __half h_x   [4194304];
__device__ __half h_wdq [1048576];
__device__ __half h_wdkv[1048576];
__device__ __half h_wkr [131072];
__device__ __half h_wqr [524288];
__device__ __half h_wo  [4194304];
__device__ __half h_wuq [1048576];
__device__ __half h_wukT[1048576];          // [h][k][d]
__device__ __half h_wuvT[1048576];          // [k'][c]
__device__ __half h_keff[16l * 512 * 512];  // keff_t[h][k][q]
__device__ __half h_veff[2048l * 512];      // veff_t[j][k']
__device__ __half h_cq  [2048l * 512];
__device__ __half h_kcat[2048l * 576];
__device__ __half h_ckvt[2l * 512 * 1024];  // [b][k'][s]
__device__ __half h_qcat[32l * 1024 * 576];
__device__ __half h_attn[32l * 1024 * 1024];
__device__ __half h_lat [32l * 1024 * 512];

struct GP {
    const __half* A; const __half* B; void* C;
    int M, N, K;
    long sA, sB, ldc;
    int aDiv, aMod, bDiv, bMod, cDiv, cMod;
    long aS1, aS2, bS1, bS2, cS1, cS2;
    int kSplit;
    int mode;    // 0 plain, 1 causal tile-skip, 2 causal k-stop
    int halfC;
};

__device__ __forceinline__ void mma_f16(float* d, const unsigned* a,
                                        const unsigned* b) {
    asm volatile(
        "mma.sync.aligned.m16n8k16.row.col.f32.f16.f16.f32 "
        "{%0,%1,%2,%3}, {%4,%5,%6,%7}, {%8,%9}, {%0,%1,%2,%3};\n"
        : "+f"(d[0]), "+f"(d[1]), "+f"(d[2]), "+f"(d[3])
        : "r"(a[0]), "r"(a[1]), "r"(a[2]), "r"(a[3]),
          "r"(b[0]), "r"(b[1]));
}

#define LDMX4(r, addr)                                                       \
    asm volatile("ldmatrix.sync.aligned.m8n8.x4.shared.b16 "                 \
                 "{%0,%1,%2,%3}, [%4];"                                      \
                 : "=r"((r)[0]), "=r"((r)[1]), "=r"((r)[2]), "=r"((r)[3])    \
                 : "r"(addr))

#define CP16(dst, src) \
    asm volatile("cp.async.cg.shared.global [%0], [%1], 16;" \
                 :: "r"(dst), "l"(src))
#define CP_COMMIT() asm volatile("cp.async.commit_group;" ::: "memory")
#define CP_WAIT1()  asm volatile("cp.async.wait_group 1;" ::: "memory")

#define SROW   40                    // halves per smem row (k32 + 8 pad)
#define BUFH   (128 * SROW)          // 5120 halves per operand per stage
#define STAGES 3
#define SMEM_BYTES (STAGES * 2 * BUFH * 2)   // 61440

// fp16 GEMM: block 128x128, k-tile 32, 4 warps (2x2), warp tile 64x64,
// 3-stage cp.async pipeline (dynamic smem), ldmatrix fragment loads.
__global__ __launch_bounds__(128) void hgemm(GP p) {
    int bmI = blockIdx.y, bnI = blockIdx.x;
    if (p.mode == 1 && bnI > bmI) return;

    int z = blockIdx.z;
    int zb = z / p.kSplit;
    int kz = z % p.kSplit;

    int kTot = p.K;
    if (p.mode == 2) { int ke = (bmI + 1) * 128; if (ke < kTot) kTot = ke; }
    int kLen = kTot / p.kSplit;

    const __half* A = p.A + (long)(zb / p.aDiv) * p.aS1 + (long)(zb % p.aMod) * p.aS2
                    + (long)kz * kLen;
    const __half* B = p.B + (long)(zb / p.bDiv) * p.bS1 + (long)(zb % p.bMod) * p.bS2
                    + (long)kz * kLen;
    char* Cb = (char*)p.C;
    long cOff = (long)(zb / p.cDiv) * p.cS1 + (long)(zb % p.cMod) * p.cS2;

    extern __shared__ __half dyn[];
    __half* AsBase = dyn;                     // [STAGES][BUFH]
    __half* BsBase = dyn + STAGES * BUFH;

    int tid  = threadIdx.x;
    int lane = tid & 31;
    int wid  = tid >> 5;
    int wm = wid >> 1, wn = wid & 1;
    int bm = bmI * 128, bn = bnI * 128;

    const __half* aBase = A + (long)(bm + tid) * p.sA;
    bool bOk = (bn + tid) < p.N;
    const __half* bBase = B + (long)(bn + tid) * p.sB;

    unsigned aSm0 = (unsigned)__cvta_generic_to_shared(AsBase) + tid * SROW * 2;
    unsigned bSm0 = (unsigned)__cvta_generic_to_shared(BsBase) + tid * SROW * 2;
    const unsigned stageB = BUFH * 2;

#define FETCH(t, slot)                                                       \
    do {                                                                     \
        const __half* ap = aBase + (long)(t) * 32;                           \
        unsigned ad = aSm0 + (unsigned)(slot) * stageB;                      \
        CP16(ad,      ap);                                                   \
        CP16(ad + 16, ap + 8);                                               \
        CP16(ad + 32, ap + 16);                                              \
        CP16(ad + 48, ap + 24);                                              \
        if (bOk) {                                                           \
            const __half* bp = bBase + (long)(t) * 32;                       \
            unsigned bd = bSm0 + (unsigned)(slot) * stageB;                  \
            CP16(bd,      bp);                                               \
            CP16(bd + 16, bp + 8);                                           \
            CP16(bd + 32, bp + 16);                                          \
            CP16(bd + 48, bp + 24);                                          \
        }                                                                    \
        CP_COMMIT();                                                         \
    } while (0)

    float acc[4][8][4];
#pragma unroll
    for (int i = 0; i < 4; i++)
#pragma unroll
        for (int j = 0; j < 8; j++)
#pragma unroll
            for (int r = 0; r < 4; r++) acc[i][j][r] = 0.f;

    int nt = kLen >> 5;   // all kLen values divisible by 32

    FETCH(0, 0);
    if (nt > 1) {
        FETCH(1, 1);
    } else {
        CP_COMMIT();
    }

    // ldmatrix per-thread addresses (slot 0, k-sub 0)
    int lrow = lane & 15;
    int lcol = (lane >> 4) * 8;
    unsigned aLd[4], bLd[4];
    unsigned aShared = (unsigned)__cvta_generic_to_shared(AsBase);
    unsigned bShared = (unsigned)__cvta_generic_to_shared(BsBase);
#pragma unroll
    for (int mi = 0; mi < 4; mi++)
        aLd[mi] = aShared + ((wm * 64 + mi * 16 + lrow) * SROW + lcol) * 2;
#pragma unroll
    for (int nj = 0; nj < 4; nj++)
        bLd[nj] = bShared + ((wn * 64 + nj * 16 + lrow) * SROW + lcol) * 2;

    int slot = 0;
    for (int t = 0; t < nt; t++) {
        CP_WAIT1();
        __syncthreads();

        if (t + 2 < nt) {
            int ns = slot + 2; if (ns >= STAGES) ns -= STAGES;
            FETCH(t + 2, ns);
        } else {
            CP_COMMIT();
        }

        unsigned so = (unsigned)slot * stageB;
#pragma unroll
        for (int ks = 0; ks < 2; ks++) {
            unsigned ko = so + ks * 32;   // +16 halves
            unsigned a[4][4], bp[4][4];
#pragma unroll
            for (int mi = 0; mi < 4; mi++) LDMX4(a[mi], aLd[mi] + ko);
#pragma unroll
            for (int nj = 0; nj < 4; nj++) LDMX4(bp[nj], bLd[nj] + ko);
#pragma unroll
            for (int mi = 0; mi < 4; mi++)
#pragma unroll
                for (int nj = 0; nj < 4; nj++) {
                    unsigned b0[2] = { bp[nj][0], bp[nj][2] };
                    unsigned b1[2] = { bp[nj][1], bp[nj][3] };
                    mma_f16(acc[mi][nj * 2],     a[mi], b0);
                    mma_f16(acc[mi][nj * 2 + 1], a[mi], b1);
                }
        }

        if (++slot == STAGES) slot = 0;
    }

    int r = lane >> 2;
    int c2 = (lane & 3) * 2;
    if (p.kSplit > 1) {
        float* C = (float*)Cb + cOff;
#pragma unroll
        for (int mi = 0; mi < 4; mi++) {
            int gm0 = bm + wm * 64 + mi * 16 + r;
#pragma unroll
            for (int ni = 0; ni < 8; ni++) {
                int gn = bn + wn * 64 + ni * 8 + c2;
                if (gn < p.N) {
                    atomicAdd(C + (long)gm0 * p.ldc + gn,     acc[mi][ni][0]);
                    atomicAdd(C + (long)gm0 * p.ldc + gn + 1, acc[mi][ni][1]);
                    atomicAdd(C + (long)(gm0 + 8) * p.ldc + gn,     acc[mi][ni][2]);
                    atomicAdd(C + (long)(gm0 + 8) * p.ldc + gn + 1, acc[mi][ni][3]);
                }
            }
        }
    } else if (p.halfC) {
        __half* C = (__half*)Cb + cOff;
#pragma unroll
        for (int mi = 0; mi < 4; mi++) {
            int gm0 = bm + wm * 64 + mi * 16 + r;
#pragma unroll
            for (int ni = 0; ni < 8; ni++) {
                int gn = bn + wn * 64 + ni * 8 + c2;
                if (gn < p.N) {
                    __half2 h0 = __floats2half2_rn(acc[mi][ni][0], acc[mi][ni][1]);
                    __half2 h1 = __floats2half2_rn(acc[mi][ni][2], acc[mi][ni][3]);
                    *(__half2*)(C + (long)gm0 * p.ldc + gn)       = h0;
                    *(__half2*)(C + (long)(gm0 + 8) * p.ldc + gn) = h1;
                }
            }
        }
    } else {
        float* C = (float*)Cb + cOff;
#pragma unroll
        for (int mi = 0; mi < 4; mi++) {
            int gm0 = bm + wm * 64 + mi * 16 + r;
#pragma unroll
            for (int ni = 0; ni < 8; ni++) {
                int gn = bn + wn * 64 + ni * 8 + c2;
                if (gn < p.N) {
                    float* cp0 = C + (long)gm0 * p.ldc + gn;
                    float* cp1 = C + (long)(gm0 + 8) * p.ldc + gn;
                    cp0[0] = acc[mi][ni][0]; cp0[1] = acc[mi][ni][1];
                    cp1[0] = acc[mi][ni][2]; cp1[1] = acc[mi][ni][3];
                }
            }
        }
    }
#undef FETCH
}

// ---------------- merged fp32 -> fp16 (7 arrays, one launch) -------------
struct F2HTab {
    const float* s[7];
    __half* d[7];
    long n[7];
};
__global__ void f2h_multi(F2HTab tab) {
    int a = blockIdx.y;
    long i = ((long)blockIdx.x * blockDim.x + threadIdx.x) * 4;
    if (i >= tab.n[a]) return;
    float4 v = *(const float4*)(tab.s[a] + i);
    __half2 h0 = __floats2half2_rn(v.x, v.y);
    __half2 h1 = __floats2half2_rn(v.z, v.w);
    *(__half2*)(tab.d[a] + i)     = h0;
    *(__half2*)(tab.d[a] + i + 2) = h1;
}

__global__ void f2h(const float* __restrict__ s, __half* __restrict__ d, long n) {
    long i = ((long)blockIdx.x * blockDim.x + threadIdx.x) * 4;
    if (i < n) {
        float4 v = *(const float4*)(s + i);
        __half2 h0 = __floats2half2_rn(v.x, v.y);
        __half2 h1 = __floats2half2_rn(v.z, v.w);
        *(__half2*)(d + i)     = h0;
        *(__half2*)(d + i + 2) = h1;
    }
}

// ---------------- transpose + convert ----------------
__global__ void transpose_h(const float* __restrict__ in, long si, long bi,
                            __half* __restrict__ out, long so, long bo) {
    __shared__ float t[32][33];
    int c0 = blockIdx.x * 32, r0 = blockIdx.y * 32;
    in  += (long)blockIdx.z * bi;
    out += (long)blockIdx.z * bo;
    int x = threadIdx.x, y = threadIdx.y;
#pragma unroll
    for (int j = 0; j < 32; j += 8)
        t[y + j][x] = in[(long)(r0 + y + j) * si + c0 + x];
    __syncthreads();
#pragma unroll
    for (int j = 0; j < 32; j += 8)
        out[(long)(c0 + y + j) * so + r0 + x] = __float2half_rn(t[x][y + j]);
}

// ---------------- RoPE ----------------
__global__ void rope_k_kernel(const float* __restrict__ ckr,
                              const float* __restrict__ fc,
                              const float* __restrict__ fs,
                              float* __restrict__ kcat) {
    int idx = blockIdx.x * blockDim.x + threadIdx.x;
    if (idx >= 2048 * 32) return;
    int m = idx >> 5, i = idx & 31;
    int t = m & 1023;
    float re = ckr[m * 64 + 2 * i], im = ckr[m * 64 + 2 * i + 1];
    float c = fc[t * 32 + i], s = fs[t * 32 + i];
    long o = (long)m * KCAT + 512 + 2 * i;
    kcat[o]     = re * c - im * s;
    kcat[o + 1] = re * s + im * c;
}

__global__ void rope_q_kernel(const float* __restrict__ cqr,
                              const float* __restrict__ fc,
                              const float* __restrict__ fs,
                              __half* __restrict__ qcat) {
    int idx = blockIdx.x * blockDim.x + threadIdx.x;
    if (idx >= 2048 * 16 * 32) return;
    int i = idx & 31;
    int h = (idx >> 5) & 15;
    int m = idx >> 9;
    int t = m & 1023, b = m >> 10;
    float re = cqr[m * 1024 + h * 64 + 2 * i];
    float im = cqr[m * 1024 + h * 64 + 2 * i + 1];
    float c = fc[t * 32 + i], s = fs[t * 32 + i];
    long o = ((long)((b * 16 + h) * 1024 + t)) * KCAT + 512 + 2 * i;
    *(__half2*)(qcat + o) = __floats2half2_rn(re * c - im * s, re * s + im * c);
}

// ---------------- causal softmax: fp32 in, fp16 out ----------------
__global__ void softmax_causal(const float* __restrict__ attn,
                               __half* __restrict__ attnh) {
    int t = blockIdx.x;
    int z = blockIdx.y;
    const float* p = attn + (long)z * 1024 * 1024 + (long)t * 1024;
    __half* ph = attnh + (long)z * 1024 * 1024 + (long)t * 1024;
    int n = t + 1;
    int lim = ((t >> 7) + 1) << 7;
    const float scale = 0.07216878364870322992f * 1.44269504088896341f;
    __shared__ float red[8];
    int tid = threadIdx.x;
    int lane = tid & 31, w = tid >> 5;

    float vals[4];
    float m = -3.4e38f;
#pragma unroll
    for (int j = 0; j < 4; j++) {
        int s = tid + j * 256;
        vals[j] = (s < n) ? p[s] * scale : -3.4e38f;
        m = fmaxf(m, vals[j]);
    }
#pragma unroll
    for (int o = 16; o > 0; o >>= 1)
        m = fmaxf(m, __shfl_xor_sync(0xffffffffu, m, o));
    if (lane == 0) red[w] = m;
    __syncthreads();
    {
        float mm = red[lane & 7];
#pragma unroll
        for (int o = 4; o > 0; o >>= 1)
            mm = fmaxf(mm, __shfl_xor_sync(0xffffffffu, mm, o));
        m = mm;
    }
    __syncthreads();

    float sum = 0.f;
#pragma unroll
    for (int j = 0; j < 4; j++) {
        int s = tid + j * 256;
        vals[j] = (s < n) ? exp2f(vals[j] - m) : 0.f;
        sum += vals[j];
    }
#pragma unroll
    for (int o = 16; o > 0; o >>= 1)
        sum += __shfl_xor_sync(0xffffffffu, sum, o);
    if (lane == 0) red[w] = sum;
    __syncthreads();
    {
        float ss = red[lane & 7];
#pragma unroll
        for (int o = 4; o > 0; o >>= 1)
            ss += __shfl_xor_sync(0xffffffffu, ss, o);
        sum = ss;
    }
    float inv = 1.f / sum;

#pragma unroll
    for (int j = 0; j < 4; j++) {
        int s = tid + j * 256;
        if (s < lim) ph[s] = __float2half_rn(vals[j] * inv);
    }
}

// ---------------- launch helpers ----------------
static void launch_gemm(const __half* A, const __half* B, void* C,
                        int M, int N, int K,
                        long sA, long sB, long ldc,
                        int batches,
                        int aDiv, long aS1, int aMod, long aS2,
                        int bDiv, long bS1, int bMod, long bS2,
                        int cDiv, long cS1, int cMod, long cS2,
                        int kSplit = 1, int mode = 0, int halfC = 0) {
    GP p;
    p.A = A; p.B = B; p.C = C;
    p.M = M; p.N = N; p.K = K;
    p.sA = sA; p.sB = sB; p.ldc = ldc;
    p.aDiv = aDiv; p.aMod = aMod; p.bDiv = bDiv; p.bMod = bMod;
    p.cDiv = cDiv; p.cMod = cMod;
    p.aS1 = aS1; p.aS2 = aS2; p.bS1 = bS1; p.bS2 = bS2; p.cS1 = cS1; p.cS2 = cS2;
    p.kSplit = kSplit; p.mode = mode; p.halfC = halfC;
    dim3 grid((N + 127) / 128, (M + 127) / 128, batches * kSplit);
    hgemm<<<grid, 128, SMEM_BYTES>>>(p);
}

static void launch_f2h(const float* s, __half* d, long n) {
    f2h<<<(unsigned)((n / 4 + 255) / 256), 256>>>(s, d, n);
}

extern "C" void kernel_launch(void* const* d_in, const int* in_sizes, int n_in,
                              void* d_out, int out_size) {
    const float* x     = (const float*)d_in[0];
    const float* fcos  = (const float*)d_in[1];
    const float* fsin  = (const float*)d_in[2];
    const float* W_dq  = (const float*)d_in[3];
    const float* W_uq  = (const float*)d_in[4];
    const float* W_dkv = (const float*)d_in[5];
    const float* W_uk  = (const float*)d_in[6];
    const float* W_uv  = (const float*)d_in[7];
    const float* W_qr  = (const float*)d_in[8];
    const float* W_kr  = (const float*)d_in[9];
    const float* W_o   = (const float*)d_in[10];
    float* out = (float*)d_out;

    static int smemSet = 0;
    if (!smemSet) {
        cudaFuncSetAttribute(hgemm, cudaFuncAttributeMaxDynamicSharedMemorySize,
                             SMEM_BYTES);
        smemSet = 1;
    }

    float *cq, *ckr, *cqr, *kcat, *veff, *attn;
    cudaGetSymbolAddress((void**)&cq,   g_cq);
    cudaGetSymbolAddress((void**)&ckr,  g_ckr);
    cudaGetSymbolAddress((void**)&cqr,  g_cqr);
    cudaGetSymbolAddress((void**)&kcat, g_kcat);
    cudaGetSymbolAddress((void**)&veff, g_veff);
    cudaGetSymbolAddress((void**)&attn, g_attn);

    __half *xh, *wdqh, *wdkvh, *wkrh, *wqrh, *woh, *wuqh, *wukT, *wuvT;
    __half *keffh, *veffh, *cqh, *kcath, *ckvth, *qcath, *attnh, *lath;
    cudaGetSymbolAddress((void**)&xh,    h_x);
    cudaGetSymbolAddress((void**)&wdqh,  h_wdq);
    cudaGetSymbolAddress((void**)&wdkvh, h_wdkv);
    cudaGetSymbolAddress((void**)&wkrh,  h_wkr);
    cudaGetSymbolAddress((void**)&wqrh,  h_wqr);
    cudaGetSymbolAddress((void**)&woh,   h_wo);
    cudaGetSymbolAddress((void**)&wuqh,  h_wuq);
    cudaGetSymbolAddress((void**)&wukT,  h_wukT);
    cudaGetSymbolAddress((void**)&wuvT,  h_wuvT);
    cudaGetSymbolAddress((void**)&keffh, h_keff);
    cudaGetSymbolAddress((void**)&veffh, h_veff);
    cudaGetSymbolAddress((void**)&cqh,   h_cq);
    cudaGetSymbolAddress((void**)&kcath, h_kcat);
    cudaGetSymbolAddress((void**)&ckvth, h_ckvt);
    cudaGetSymbolAddress((void**)&qcath, h_qcat);
    cudaGetSymbolAddress((void**)&attnh, h_attn);
    cudaGetSymbolAddress((void**)&lath,  h_lat);

    cudaMemsetAsync(veff, 0, 2048l * 512 * 4);
    cudaMemsetAsync(cq,   0, 2048l * 512 * 4);
    cudaMemsetAsync(ckr,  0, 2048l * 64 * 4);
    cudaMemsetAsync(cqr,  0, 2048l * 1024 * 4);
    cudaMemsetAsync(kcat, 0, 2048l * 576 * 4);

    // 0) convert inputs to fp16 (one merged launch) + transposes
    {
        F2HTab tab;
        tab.s[0] = x;     tab.d[0] = xh;    tab.n[0] = 4194304;
        tab.s[1] = W_o;   tab.d[1] = woh;   tab.n[1] = 4194304;
        tab.s[2] = W_dq;  tab.d[2] = wdqh;  tab.n[2] = 1048576;
        tab.s[3] = W_dkv; tab.d[3] = wdkvh; tab.n[3] = 1048576;
        tab.s[4] = W_uq;  tab.d[4] = wuqh;  tab.n[4] = 1048576;
        tab.s[5] = W_qr;  tab.d[5] = wqrh;  tab.n[5] = 524288;
        tab.s[6] = W_kr;  tab.d[6] = wkrh;  tab.n[6] = 131072;
        dim3 g(4096, 7);
        f2h_multi<<<g, 256>>>(tab);
    }
    {   // wukT[h][k][d] = W_uk[(h*128+d)*512 + k]
        dim3 g(512 / 32, 128 / 32, 16), b(32, 8);
        transpose_h<<<g, b>>>(W_uk, 512, 128l * 512, wukT, 128, 512l * 128);
    }
    {   // wuvT[k'][c] = W_uv[c*512 + k']
        dim3 g(512 / 32, 2048 / 32, 1), b(32, 8);
        transpose_h<<<g, b>>>(W_uv, 512, 0, wuvT, 2048, 0);
    }

    // 1) keff_t[h][k][q]  (halfC)
    launch_gemm(wukT, wuqh, keffh, 512, 512, 128,
                128, 2048, 512, 16,
                1, 0, 16, 512l * 128,
                1, 0, 16, 128,
                1, 0, 16, 512l * 512, 1, 0, 1);

    // 2) veff_t[j][k']  (split-K 8)
    launch_gemm(woh, wuvT, veff, 2048, 512, 2048,
                2048, 2048, 512, 1,
                1, 0, 1, 0, 1, 0, 1, 0, 1, 0, 1, 0, 8);
    launch_f2h(veff, veffh, 1048576);

    // 3) c_q  (split-K 8)
    launch_gemm(xh, wdqh, cq, 2048, 512, 2048,
                2048, 2048, 512, 1,
                1, 0, 1, 0, 1, 0, 1, 0, 1, 0, 1, 0, 8);
    launch_f2h(cq, cqh, 1048576);

    // 4) c_kv -> kcat cols [0,512)  (split-K 8)
    launch_gemm(xh, wdkvh, kcat, 2048, 512, 2048,
                2048, 2048, KCAT, 1,
                1, 0, 1, 0, 1, 0, 1, 0, 1, 0, 1, 0, 8);

    // 5) c_kr  (split-K 16)
    launch_gemm(xh, wkrh, ckr, 2048, 64, 2048,
                2048, 2048, 64, 1,
                1, 0, 1, 0, 1, 0, 1, 0, 1, 0, 1, 0, 16);

    // 6) c_qr  (split-K 4)
    launch_gemm(cqh, wqrh, cqr, 2048, 1024, 512,
                512, 512, 1024, 1,
                1, 0, 1, 0, 1, 0, 1, 0, 1, 0, 1, 0, 4);

    // 7) RoPE k, then kcat -> fp16 + c_kv transpose
    rope_k_kernel<<<(2048 * 32 + 255) / 256, 256>>>(ckr, fcos, fsin, kcat);
    launch_f2h(kcat, kcath, 2048l * 576);
    {
        dim3 g(512 / 32, 1024 / 32, 2), b(32, 8);
        transpose_h<<<g, b>>>(kcat, 576, 1024l * 576, ckvth, 1024, 512l * 1024);
    }

    // 8) RoPE q -> qcath cols [512,576)
    rope_q_kernel<<<(2048 * 16 * 32 + 255) / 256, 256>>>(cqr, fcos, fsin, qcath);

    // 9) q_abs  (halfC)
    launch_gemm(cqh, keffh, qcath, 1024, 512, 512,
                512, 512, KCAT, 32,
                16, 1024l * 512, 1, 0,
                1, 0, 16, 512l * 512,
                1, 0, 32, 1024l * KCAT, 1, 0, 1);

    // 10) logits  (causal tile-skip; fp32 out)
    launch_gemm(qcath, kcath, attn, 1024, 1024, KCAT,
                KCAT, KCAT, 1024, 32,
                1, 0, 32, 1024l * KCAT,
                16, 1024l * KCAT, 1, 0,
                1, 0, 32, 1024l * 1024, 1, 1);

    // 11) softmax
    {
        dim3 grid(1024, 32);
        softmax_causal<<<grid, 256>>>(attn, attnh);
    }

    // 12) lat  (causal k-stop; halfC)
    launch_gemm(attnh, ckvth, lath, 1024, 512, 1024,
                1024, 1024, 512, 32,
                1, 0, 32, 1024l * 1024,
                16, 512l * 1024, 1, 0,
                1, 0, 32, 1024l * 512, 1, 2, 1);

    // 13) y = lat @ veff_t^T  (fp32 out)
    launch_gemm(lath, veffh, out, 1024, 128, 512,
                512, 512, 2048, 32,
                1, 0, 32, 1024l * 512,
                1, 0, 16, 128l * 512,
                16, 1024l * 2048, 16, 128);
}

// round 16
// speedup vs baseline: 1.0956x; 1.0956x over previous
#include <cuda_runtime.h>
#include <cuda_fp16.h>
#include <math.h>

#define BB   2
#define TT   1024
#define CC   2048
#define NH   16
#define HS   128
#define NLQ  512
#define NLKV 512
#define DHR  64
#define KCAT 576

// ---------------- fp32 scratch ----------------
__device__ float g_cq  [2048l * 512];
__device__ float g_ckr [2048l * 64];
__device__ float g_cqr [2048l * 1024];
__device__ float g_kcat[2048l * 576];
__device__ float g_veff[2048l * 512];
__device__ float g_attn[32l * 1024 * 1024];

// ---------------- fp16 scratch (all GEMM operands K-contiguous) ----------
__device__ __half h_x   [4194304];
__device__ __half h_wdq [1048576];
__device__ __half h_wdkv[1048576];
__device__ __half h_wkr [131072];
__device__ __half h_wqr [524288];
__device__ __half h_wo  [4194304];
__device__ __half h_wuq [1048576];
__device__ __half h_wukT[1048576];          // [h][k][d]
__device__ __half h_wuvT[1048576];          // [k'][c]
__device__ __half h_keff[16l * 512 * 512];  // keff_t[h][k][q]
__device__ __half h_veff[2048l * 512];      // veff_t[j][k']
__device__ __half h_cq  [2048l * 512];
__device__ __half h_kcat[2048l * 576];
__device__ __half h_ckvt[2l * 512 * 1024];  // [b][k'][s]
__device__ __half h_qcat[32l * 1024 * 576];
__device__ __half h_attn[32l * 1024 * 1024];
__device__ __half h_lat [32l * 1024 * 512];

struct GP {
    const __half* A; const __half* B; void* C;
    int M, N, K;
    long sA, sB, ldc;
    int aDiv, aMod, bDiv, bMod, cDiv, cMod;
    long aS1, aS2, bS1, bS2, cS1, cS2;
    int kSplit;
    int mode;    // 0 plain, 1 causal tile-skip, 2 causal k-stop
    int halfC;
};

__device__ __forceinline__ void mma_f16(float* d, const unsigned* a,
                                        const unsigned* b) {
    asm volatile(
        "mma.sync.aligned.m16n8k16.row.col.f32.f16.f16.f32 "
        "{%0,%1,%2,%3}, {%4,%5,%6,%7}, {%8,%9}, {%0,%1,%2,%3};\n"
        : "+f"(d[0]), "+f"(d[1]), "+f"(d[2]), "+f"(d[3])
        : "r"(a[0]), "r"(a[1]), "r"(a[2]), "r"(a[3]),
          "r"(b[0]), "r"(b[1]));
}

#define CP16(dst, src) \
    asm volatile("cp.async.cg.shared.global [%0], [%1], 16;" \
                 :: "r"(dst), "l"(src))
#define CP_COMMIT() asm volatile("cp.async.commit_group;" ::: "memory")
#define CP_WAIT1()  asm volatile("cp.async.wait_group 1;" ::: "memory")

#define SROW   24            // halves per smem row (bank-conflict free)
#define BUFW   (128 * SROW)  // 3072 halves per operand per stage
#define STAGES 3

// fp16 GEMM: block 128x128, k-tile 16, 4 warps (2x2), warp tile 64x64,
// 3-stage cp.async pipeline, all operands K-contiguous [row][k] fp16.
__global__ void __launch_bounds__(128, 3) hgemm(GP p) {
    int bmI = blockIdx.y, bnI = blockIdx.x;
    if (p.mode == 1 && bnI > bmI) return;

    int z = blockIdx.z;
    int zb = z / p.kSplit;
    int kz = z % p.kSplit;

    int kTot = p.K;
    if (p.mode == 2) { int ke = (bmI + 1) * 128; if (ke < kTot) kTot = ke; }
    int kLen = kTot / p.kSplit;

    const __half* A = p.A + (long)(zb / p.aDiv) * p.aS1 + (long)(zb % p.aMod) * p.aS2
                    + (long)kz * kLen;
    const __half* B = p.B + (long)(zb / p.bDiv) * p.bS1 + (long)(zb % p.bMod) * p.bS2
                    + (long)kz * kLen;
    char* Cb = (char*)p.C;
    long cOff = (long)(zb / p.cDiv) * p.cS1 + (long)(zb % p.cMod) * p.cS2;

    __shared__ __align__(16) __half As[STAGES][BUFW];
    __shared__ __align__(16) __half Bs[STAGES][BUFW];

    int tid  = threadIdx.x;
    int lane = tid & 31;
    int wid  = tid >> 5;
    int wm = wid >> 1, wn = wid & 1;
    int bm = bmI * 128, bn = bnI * 128;

    const __half* aBase = A + (long)(bm + tid) * p.sA;
    bool bOk = (bn + tid) < p.N;
    const __half* bBase = B + (long)(bn + tid) * p.sB;

    unsigned aSm[STAGES], bSm[STAGES];
#pragma unroll
    for (int s = 0; s < STAGES; s++) {
        aSm[s] = (unsigned)__cvta_generic_to_shared(&As[s][tid * SROW]);
        bSm[s] = (unsigned)__cvta_generic_to_shared(&Bs[s][tid * SROW]);
    }

#define FETCH(t, slot)                                                       \
    do {                                                                     \
        const __half* ap = aBase + (long)(t) * 16;                           \
        CP16(aSm[slot],      ap);                                            \
        CP16(aSm[slot] + 16, ap + 8);                                        \
        if (bOk) {                                                           \
            const __half* bp = bBase + (long)(t) * 16;                       \
            CP16(bSm[slot],      bp);                                        \
            CP16(bSm[slot] + 16, bp + 8);                                    \
        }                                                                    \
        CP_COMMIT();                                                         \
    } while (0)

    float acc[4][8][4];
#pragma unroll
    for (int i = 0; i < 4; i++)
#pragma unroll
        for (int j = 0; j < 8; j++)
#pragma unroll
            for (int r = 0; r < 4; r++) acc[i][j][r] = 0.f;

    int nt = kLen >> 4;   // all kLen values divisible by 16

    FETCH(0, 0);
    if (nt > 1) {
        FETCH(1, 1);
    } else {
        CP_COMMIT();
    }

    int r = lane >> 2, c = lane & 3;

    unsigned aAddr[4], bAddr[8];
#pragma unroll
    for (int mi = 0; mi < 4; mi++)
        aAddr[mi] = (unsigned)(wm * 64 + mi * 16 + r) * (SROW / 2) + (unsigned)c;
#pragma unroll
    for (int ni = 0; ni < 8; ni++)
        bAddr[ni] = (unsigned)(wn * 64 + ni * 8 + r) * (SROW / 2) + (unsigned)c;
    const unsigned aM8 = 8u * (SROW / 2);
    const unsigned k8  = 4u;

    int slot = 0;
    for (int t = 0; t < nt; t++) {
        CP_WAIT1();
        __syncthreads();

        if (t + 2 < nt) {
            int ns = slot + 2; if (ns >= STAGES) ns -= STAGES;
            FETCH(t + 2, ns);
        } else {
            CP_COMMIT();
        }

        const unsigned* sa = (const unsigned*)&As[slot][0];
        const unsigned* sb = (const unsigned*)&Bs[slot][0];
        unsigned a[4][4], b[8][2];
#pragma unroll
        for (int mi = 0; mi < 4; mi++) {
            unsigned o = aAddr[mi];
            a[mi][0] = sa[o];
            a[mi][1] = sa[o + aM8];
            a[mi][2] = sa[o + k8];
            a[mi][3] = sa[o + aM8 + k8];
        }
#pragma unroll
        for (int ni = 0; ni < 8; ni++) {
            unsigned o = bAddr[ni];
            b[ni][0] = sb[o];
            b[ni][1] = sb[o + k8];
        }
#pragma unroll
        for (int mi = 0; mi < 4; mi++)
#pragma unroll
            for (int ni = 0; ni < 8; ni++)
                mma_f16(acc[mi][ni], a[mi], b[ni]);

        if (++slot == STAGES) slot = 0;
    }

    int c2 = (lane & 3) * 2;
    if (p.kSplit > 1) {
        float* C = (float*)Cb + cOff;
#pragma unroll
        for (int mi = 0; mi < 4; mi++) {
            int gm0 = bm + wm * 64 + mi * 16 + r;
#pragma unroll
            for (int ni = 0; ni < 8; ni++) {
                int gn = bn + wn * 64 + ni * 8 + c2;
                if (gn < p.N) {
                    atomicAdd(C + (long)gm0 * p.ldc + gn,     acc[mi][ni][0]);
                    atomicAdd(C + (long)gm0 * p.ldc + gn + 1, acc[mi][ni][1]);
                    atomicAdd(C + (long)(gm0 + 8) * p.ldc + gn,     acc[mi][ni][2]);
                    atomicAdd(C + (long)(gm0 + 8) * p.ldc + gn + 1, acc[mi][ni][3]);
                }
            }
        }
    } else if (p.halfC) {
        __half* C = (__half*)Cb + cOff;
#pragma unroll
        for (int mi = 0; mi < 4; mi++) {
            int gm0 = bm + wm * 64 + mi * 16 + r;
#pragma unroll
            for (int ni = 0; ni < 8; ni++) {
                int gn = bn + wn * 64 + ni * 8 + c2;
                if (gn < p.N) {
                    __half2 h0 = __floats2half2_rn(acc[mi][ni][0], acc[mi][ni][1]);
                    __half2 h1 = __floats2half2_rn(acc[mi][ni][2], acc[mi][ni][3]);
                    *(__half2*)(C + (long)gm0 * p.ldc + gn)       = h0;
                    *(__half2*)(C + (long)(gm0 + 8) * p.ldc + gn) = h1;
                }
            }
        }
    } else {
        float* C = (float*)Cb + cOff;
#pragma unroll
        for (int mi = 0; mi < 4; mi++) {
            int gm0 = bm + wm * 64 + mi * 16 + r;
#pragma unroll
            for (int ni = 0; ni < 8; ni++) {
                int gn = bn + wn * 64 + ni * 8 + c2;
                if (gn < p.N) {
                    float* cp0 = C + (long)gm0 * p.ldc + gn;
                    float* cp1 = C + (long)(gm0 + 8) * p.ldc + gn;
                    cp0[0] = acc[mi][ni][0]; cp0[1] = acc[mi][ni][1];
                    cp1[0] = acc[mi][ni][2]; cp1[1] = acc[mi][ni][3];
                }
            }
        }
    }
#undef FETCH
}

// ---------------- merged fp32 -> fp16 (7 arrays, one launch) -------------
struct F2HTab {
    const float* s[7];
    __half* d[7];
    long n[7];
};
__global__ void f2h_multi(F2HTab tab) {
    int a = blockIdx.y;
    long i = ((long)blockIdx.x * blockDim.x + threadIdx.x) * 4;
    if (i >= tab.n[a]) return;
    float4 v = *(const float4*)(tab.s[a] + i);
    __half2 h0 = __floats2half2_rn(v.x, v.y);
    __half2 h1 = __floats2half2_rn(v.z, v.w);
    *(__half2*)(tab.d[a] + i)     = h0;
    *(__half2*)(tab.d[a] + i + 2) = h1;
}

__global__ void f2h(const float* __restrict__ s, __half* __restrict__ d, long n) {
    long i = ((long)blockIdx.x * blockDim.x + threadIdx.x) * 4;
    if (i < n) {
        float4 v = *(const float4*)(s + i);
        __half2 h0 = __floats2half2_rn(v.x, v.y);
        __half2 h1 = __floats2half2_rn(v.z, v.w);
        *(__half2*)(d + i)     = h0;
        *(__half2*)(d + i + 2) = h1;
    }
}

// ---------------- transpose + convert ----------------
__global__ void transpose_h(const float* __restrict__ in, long si, long bi,
                            __half* __restrict__ out, long so, long bo) {
    __shared__ float t[32][33];
    int c0 = blockIdx.x * 32, r0 = blockIdx.y * 32;
    in  += (long)blockIdx.z * bi;
    out += (long)blockIdx.z * bo;
    int x = threadIdx.x, y = threadIdx.y;
#pragma unroll
    for (int j = 0; j < 32; j += 8)
        t[y + j][x] = in[(long)(r0 + y + j) * si + c0 + x];
    __syncthreads();
#pragma unroll
    for (int j = 0; j < 32; j += 8)
        out[(long)(c0 + y + j) * so + r0 + x] = __float2half_rn(t[x][y + j]);
}

// ---------------- RoPE ----------------
__global__ void rope_k_kernel(const float* __restrict__ ckr,
                              const float* __restrict__ fc,
                              const float* __restrict__ fs,
                              float* __restrict__ kcat) {
    int idx = blockIdx.x * blockDim.x + threadIdx.x;
    if (idx >= 2048 * 32) return;
    int m = idx >> 5, i = idx & 31;
    int t = m & 1023;
    float re = ckr[m * 64 + 2 * i], im = ckr[m * 64 + 2 * i + 1];
    float c = fc[t * 32 + i], s = fs[t * 32 + i];
    long o = (long)m * KCAT + 512 + 2 * i;
    kcat[o]     = re * c - im * s;
    kcat[o + 1] = re * s + im * c;
}

__global__ void rope_q_kernel(const float* __restrict__ cqr,
                              const float* __restrict__ fc,
                              const float* __restrict__ fs,
                              __half* __restrict__ qcat) {
    int idx = blockIdx.x * blockDim.x + threadIdx.x;
    if (idx >= 2048 * 16 * 32) return;
    int i = idx & 31;
    int h = (idx >> 5) & 15;
    int m = idx >> 9;
    int t = m & 1023, b = m >> 10;
    float re = cqr[m * 1024 + h * 64 + 2 * i];
    float im = cqr[m * 1024 + h * 64 + 2 * i + 1];
    float c = fc[t * 32 + i], s = fs[t * 32 + i];
    long o = ((long)((b * 16 + h) * 1024 + t)) * KCAT + 512 + 2 * i;
    *(__half2*)(qcat + o) = __floats2half2_rn(re * c - im * s, re * s + im * c);
}

// ---------------- causal softmax: fp32 in, fp16 out ----------------
__global__ void softmax_causal(const float* __restrict__ attn,
                               __half* __restrict__ attnh) {
    int t = blockIdx.x;
    int z = blockIdx.y;
    const float* p = attn + (long)z * 1024 * 1024 + (long)t * 1024;
    __half* ph = attnh + (long)z * 1024 * 1024 + (long)t * 1024;
    int n = t + 1;
    int lim = ((t >> 7) + 1) << 7;
    const float scale = 0.07216878364870322992f * 1.44269504088896341f;
    __shared__ float red[8];
    int tid = threadIdx.x;
    int lane = tid & 31, w = tid >> 5;

    float vals[4];
    float m = -3.4e38f;
#pragma unroll
    for (int j = 0; j < 4; j++) {
        int s = tid + j * 256;
        vals[j] = (s < n) ? p[s] * scale : -3.4e38f;
        m = fmaxf(m, vals[j]);
    }
#pragma unroll
    for (int o = 16; o > 0; o >>= 1)
        m = fmaxf(m, __shfl_xor_sync(0xffffffffu, m, o));
    if (lane == 0) red[w] = m;
    __syncthreads();
    {
        float mm = red[lane & 7];
#pragma unroll
        for (int o = 4; o > 0; o >>= 1)
            mm = fmaxf(mm, __shfl_xor_sync(0xffffffffu, mm, o));
        m = mm;
    }
    __syncthreads();

    float sum = 0.f;
#pragma unroll
    for (int j = 0; j < 4; j++) {
        int s = tid + j * 256;
        vals[j] = (s < n) ? exp2f(vals[j] - m) : 0.f;
        sum += vals[j];
    }
#pragma unroll
    for (int o = 16; o > 0; o >>= 1)
        sum += __shfl_xor_sync(0xffffffffu, sum, o);
    if (lane == 0) red[w] = sum;
    __syncthreads();
    {
        float ss = red[lane & 7];
#pragma unroll
        for (int o = 4; o > 0; o >>= 1)
            ss += __shfl_xor_sync(0xffffffffu, ss, o);
        sum = ss;
    }
    float inv = 1.f / sum;

#pragma unroll
    for (int j = 0; j < 4; j++) {
        int s = tid + j * 256;
        if (s < lim) ph[s] = __float2half_rn(vals[j] * inv);
    }
}

// ---------------- launch helpers ----------------
static void launch_gemm(const __half* A, const __half* B, void* C,
                        int M, int N, int K,
                        long sA, long sB, long ldc,
                        int batches,
                        int aDiv, long aS1, int aMod, long aS2,
                        int bDiv, long bS1, int bMod, long bS2,
                        int cDiv, long cS1, int cMod, long cS2,
                        int kSplit = 1, int mode = 0, int halfC = 0) {
    GP p;
    p.A = A; p.B = B; p.C = C;
    p.M = M; p.N = N; p.K = K;
    p.sA = sA; p.sB = sB; p.ldc = ldc;
    p.aDiv = aDiv; p.aMod = aMod; p.bDiv = bDiv; p.bMod = bMod;
    p.cDiv = cDiv; p.cMod = cMod;
    p.aS1 = aS1; p.aS2 = aS2; p.bS1 = bS1; p.bS2 = bS2; p.cS1 = cS1; p.cS2 = cS2;
    p.kSplit = kSplit; p.mode = mode; p.halfC = halfC;
    dim3 grid((N + 127) / 128, (M + 127) / 128, batches * kSplit);
    hgemm<<<grid, 128>>>(p);
}

static void launch_f2h(const float* s, __half* d, long n) {
    f2h<<<(unsigned)((n / 4 + 255) / 256), 256>>>(s, d, n);
}

extern "C" void kernel_launch(void* const* d_in, const int* in_sizes, int n_in,
                              void* d_out, int out_size) {
    const float* x     = (const float*)d_in[0];
    const float* fcos  = (const float*)d_in[1];
    const float* fsin  = (const float*)d_in[2];
    const float* W_dq  = (const float*)d_in[3];
    const float* W_uq  = (const float*)d_in[4];
    const float* W_dkv = (const float*)d_in[5];
    const float* W_uk  = (const float*)d_in[6];
    const float* W_uv  = (const float*)d_in[7];
    const float* W_qr  = (const float*)d_in[8];
    const float* W_kr  = (const float*)d_in[9];
    const float* W_o   = (const float*)d_in[10];
    float* out = (float*)d_out;

    float *cq, *ckr, *cqr, *kcat, *veff, *attn;
    cudaGetSymbolAddress((void**)&cq,   g_cq);
    cudaGetSymbolAddress((void**)&ckr,  g_ckr);
    cudaGetSymbolAddress((void**)&cqr,  g_cqr);
    cudaGetSymbolAddress((void**)&kcat, g_kcat);
    cudaGetSymbolAddress((void**)&veff, g_veff);
    cudaGetSymbolAddress((void**)&attn, g_attn);

    __half *xh, *wdqh, *wdkvh, *wkrh, *wqrh, *woh, *wuqh, *wukT, *wuvT;
    __half *keffh, *veffh, *cqh, *kcath, *ckvth, *qcath, *attnh, *lath;
    cudaGetSymbolAddress((void**)&xh,    h_x);
    cudaGetSymbolAddress((void**)&wdqh,  h_wdq);
    cudaGetSymbolAddress((void**)&wdkvh, h_wdkv);
    cudaGetSymbolAddress((void**)&wkrh,  h_wkr);
    cudaGetSymbolAddress((void**)&wqrh,  h_wqr);
    cudaGetSymbolAddress((void**)&woh,   h_wo);
    cudaGetSymbolAddress((void**)&wuqh,  h_wuq);
    cudaGetSymbolAddress((void**)&wukT,  h_wukT);
    cudaGetSymbolAddress((void**)&wuvT,  h_wuvT);
    cudaGetSymbolAddress((void**)&keffh, h_keff);
    cudaGetSymbolAddress((void**)&veffh, h_veff);
    cudaGetSymbolAddress((void**)&cqh,   h_cq);
    cudaGetSymbolAddress((void**)&kcath, h_kcat);
    cudaGetSymbolAddress((void**)&ckvth, h_ckvt);
    cudaGetSymbolAddress((void**)&qcath, h_qcat);
    cudaGetSymbolAddress((void**)&attnh, h_attn);
    cudaGetSymbolAddress((void**)&lath,  h_lat);

    cudaMemsetAsync(veff, 0, 2048l * 512 * 4);
    cudaMemsetAsync(cq,   0, 2048l * 512 * 4);
    cudaMemsetAsync(ckr,  0, 2048l * 64 * 4);
    cudaMemsetAsync(cqr,  0, 2048l * 1024 * 4);
    cudaMemsetAsync(kcat, 0, 2048l * 576 * 4);

    // 0) convert inputs to fp16 (one merged launch) + transposes
    {
        F2HTab tab;
        tab.s[0] = x;     tab.d[0] = xh;    tab.n[0] = 4194304;
        tab.s[1] = W_o;   tab.d[1] = woh;   tab.n[1] = 4194304;
        tab.s[2] = W_dq;  tab.d[2] = wdqh;  tab.n[2] = 1048576;
        tab.s[3] = W_dkv; tab.d[3] = wdkvh; tab.n[3] = 1048576;
        tab.s[4] = W_uq;  tab.d[4] = wuqh;  tab.n[4] = 1048576;
        tab.s[5] = W_qr;  tab.d[5] = wqrh;  tab.n[5] = 524288;
        tab.s[6] = W_kr;  tab.d[6] = wkrh;  tab.n[6] = 131072;
        dim3 g(4096, 7);
        f2h_multi<<<g, 256>>>(tab);
    }
    {   // wukT[h][k][d] = W_uk[(h*128+d)*512 + k]
        dim3 g(512 / 32, 128 / 32, 16), b(32, 8);
        transpose_h<<<g, b>>>(W_uk, 512, 128l * 512, wukT, 128, 512l * 128);
    }
    {   // wuvT[k'][c] = W_uv[c*512 + k']
        dim3 g(512 / 32, 2048 / 32, 1), b(32, 8);
        transpose_h<<<g, b>>>(W_uv, 512, 0, wuvT, 2048, 0);
    }

    // 1) keff_t[h][k][q]  (halfC)
    launch_gemm(wukT, wuqh, keffh, 512, 512, 128,
                128, 2048, 512, 16,
                1, 0, 16, 512l * 128,
                1, 0, 16, 128,
                1, 0, 16, 512l * 512, 1, 0, 1);

    // 2) veff_t[j][k']  (split-K 8)
    launch_gemm(woh, wuvT, veff, 2048, 512, 2048,
                2048, 2048, 512, 1,
                1, 0, 1, 0, 1, 0, 1, 0, 1, 0, 1, 0, 8);
    launch_f2h(veff, veffh, 1048576);

    // 3) c_q  (split-K 8)
    launch_gemm(xh, wdqh, cq, 2048, 512, 2048,
                2048, 2048, 512, 1,
                1, 0, 1, 0, 1, 0, 1, 0, 1, 0, 1, 0, 8);
    launch_f2h(cq, cqh, 1048576);

    // 4) c_kv -> kcat cols [0,512)  (split-K 8)
    launch_gemm(xh, wdkvh, kcat, 2048, 512, 2048,
                2048, 2048, KCAT, 1,
                1, 0, 1, 0, 1, 0, 1, 0, 1, 0, 1, 0, 8);

    // 5) c_kr  (split-K 16)
    launch_gemm(xh, wkrh, ckr, 2048, 64, 2048,
                2048, 2048, 64, 1,
                1, 0, 1, 0, 1, 0, 1, 0, 1, 0, 1, 0, 16);

    // 6) c_qr  (split-K 4)
    launch_gemm(cqh, wqrh, cqr, 2048, 1024, 512,
                512, 512, 1024, 1,
                1, 0, 1, 0, 1, 0, 1, 0, 1, 0, 1, 0, 4);

    // 7) RoPE k, then kcat -> fp16 + c_kv transpose
    rope_k_kernel<<<(2048 * 32 + 255) / 256, 256>>>(ckr, fcos, fsin, kcat);
    launch_f2h(kcat, kcath, 2048l * 576);
    {
        dim3 g(512 / 32, 1024 / 32, 2), b(32, 8);
        transpose_h<<<g, b>>>(kcat, 576, 1024l * 576, ckvth, 1024, 512l * 1024);
    }

    // 8) RoPE q -> qcath cols [512,576)
    rope_q_kernel<<<(2048 * 16 * 32 + 255) / 256, 256>>>(cqr, fcos, fsin, qcath);

    // 9) q_abs  (halfC)
    launch_gemm(cqh, keffh, qcath, 1024, 512, 512,
                512, 512, KCAT, 32,
                16, 1024l * 512, 1, 0,
                1, 0, 16, 512l * 512,
                1, 0, 32, 1024l * KCAT, 1, 0, 1);

    // 10) logits  (causal tile-skip; fp32 out)
    launch_gemm(qcath, kcath, attn, 1024, 1024, KCAT,
                KCAT, KCAT, 1024, 32,
                1, 0, 32, 1024l * KCAT,
                16, 1024l * KCAT, 1, 0,
                1, 0, 32, 1024l * 1024, 1, 1);

    // 11) softmax
    {
        dim3 grid(1024, 32);
        softmax_causal<<<grid, 256>>>(attn, attnh);
    }

    // 12) lat  (causal k-stop; halfC)
    launch_gemm(attnh, ckvth, lath, 1024, 512, 1024,
                1024, 1024, 512, 32,
                1, 0, 32, 1024l * 1024,
                16, 512l * 1024, 1, 0,
                1, 0, 32, 1024l * 512, 1, 2, 1);

    // 13) y = lat @ veff_t^T  (fp32 out)
    launch_gemm(lath, veffh, out, 1024, 128, 512,
                512, 512, 2048, 32,
                1, 0, 32, 1024l * 512,
                1, 0, 16, 128l * 512,
                16, 1024l * 2048, 16, 128);
}